// round 9
// baseline (speedup 1.0000x reference)
#include <cuda_runtime.h>

// NormalizedCrossCorrelation via Parseval identity:
//   sum_k |X_k|^2 = nt * sum_n x_n^2  =>  Ex = DT * sum(x^2) + EPS
//   cc = sum(x*y) / sqrt(Ex*Ey), masked by max|x|>0, summed over all columns.
//
// x,y: [nt=4096, ncol=3072] row-major (columns contiguous).
//
// SINGLE fused kernel, grid (6, 32) x 512 threads (4 time-slices x 128 col4).
//  * Stream phase: each thread streams 32 rows (double-buffered, 8 LDG.128 in
//    flight); slices 1-3 spill to smem, slice 0 folds and writes ONE partial
//    per (split=blockIdx.y, col4) to 1.5 MB L2-resident scratch.
//  * Finish phase: per-column-block counters; the LAST of the 32 y-blocks for
//    a given blockIdx.x reduces its 32 splits x 128 col4 (256 KB, __ldcg),
//    computes cc per column, block-reduces, one atomicAdd into out.
//  * Counters self-reset to 0 (graph-replay safe). Block (0,0) zeroes out[0]
//    at start; all finishers complete strictly later.

#define NT              4096
#define NCOL            3072
#define NC4             768          // NCOL / 4
#define SPLITS          32           // = grid.y
#define SLICES          4
#define COLS_PER_BLK    128
#define ROWS_PER_THREAD 32           // NT / SPLITS / SLICES
#define BLK1            (SLICES * COLS_PER_BLK)   // 512
#define COL_BLOCKS      6            // NC4 / COLS_PER_BLK
#define DT_CONST        0.001f
#define EPS_CONST       1e-10f

__device__ float4 g_sx2[SPLITS * NC4];
__device__ float4 g_sy2[SPLITS * NC4];
__device__ float4 g_sxy[SPLITS * NC4];
__device__ float4 g_mx [SPLITS * NC4];
__device__ unsigned int g_count[COL_BLOCKS];   // zero-init; reset by finisher

__device__ __forceinline__ void accum(const float4 xv, const float4 yv,
                                      float4& sx2, float4& sy2,
                                      float4& sxy, float4& mx) {
    sx2.x = fmaf(xv.x, xv.x, sx2.x);
    sx2.y = fmaf(xv.y, xv.y, sx2.y);
    sx2.z = fmaf(xv.z, xv.z, sx2.z);
    sx2.w = fmaf(xv.w, xv.w, sx2.w);
    sy2.x = fmaf(yv.x, yv.x, sy2.x);
    sy2.y = fmaf(yv.y, yv.y, sy2.y);
    sy2.z = fmaf(yv.z, yv.z, sy2.z);
    sy2.w = fmaf(yv.w, yv.w, sy2.w);
    sxy.x = fmaf(xv.x, yv.x, sxy.x);
    sxy.y = fmaf(xv.y, yv.y, sxy.y);
    sxy.z = fmaf(xv.z, yv.z, sxy.z);
    sxy.w = fmaf(xv.w, yv.w, sxy.w);
    mx.x = fmaxf(mx.x, fabsf(xv.x));
    mx.y = fmaxf(mx.y, fabsf(xv.y));
    mx.z = fmaxf(mx.z, fabsf(xv.z));
    mx.w = fmaxf(mx.w, fabsf(xv.w));
}

__device__ __forceinline__ float4 ldcg4(const float4* p) {
    return __ldcg(p);
}

__global__ __launch_bounds__(BLK1, 2) void ncc_fused(const float4* __restrict__ x,
                                                     const float4* __restrict__ y,
                                                     float* __restrict__ out) {
    if (blockIdx.x == 0 && blockIdx.y == 0 && threadIdx.x == 0)
        out[0] = 0.0f;   // all finishers complete strictly after wave-1 start

    const int c     = threadIdx.x & (COLS_PER_BLK - 1);   // 0..127
    const int slice = threadIdx.x >> 7;                   // 0..3
    const int bx    = blockIdx.x;
    const int col4  = bx * COLS_PER_BLK + c;              // 0..767
    const int row0  = blockIdx.y * (SLICES * ROWS_PER_THREAD) + slice * ROWS_PER_THREAD;

    float4 sx2 = make_float4(0.f, 0.f, 0.f, 0.f);
    float4 sy2 = make_float4(0.f, 0.f, 0.f, 0.f);
    float4 sxy = make_float4(0.f, 0.f, 0.f, 0.f);
    float4 mx  = make_float4(0.f, 0.f, 0.f, 0.f);

    const float4* xp = x + (size_t)row0 * NC4 + col4;
    const float4* yp = y + (size_t)row0 * NC4 + col4;

    // Double-buffered, 4 rows per stage: 8 LDG.128 always in flight.
    float4 xa0, xa1, xa2, xa3, ya0, ya1, ya2, ya3;
    xa0 = __ldcs(xp + 0 * NC4);
    xa1 = __ldcs(xp + 1 * NC4);
    xa2 = __ldcs(xp + 2 * NC4);
    xa3 = __ldcs(xp + 3 * NC4);
    ya0 = __ldcs(yp + 0 * NC4);
    ya1 = __ldcs(yp + 1 * NC4);
    ya2 = __ldcs(yp + 2 * NC4);
    ya3 = __ldcs(yp + 3 * NC4);

#pragma unroll
    for (int r = 4; r < ROWS_PER_THREAD; r += 4) {
        const float4* xn = xp + (size_t)r * NC4;
        const float4* yn = yp + (size_t)r * NC4;
        const float4 xb0 = __ldcs(xn + 0 * NC4);
        const float4 xb1 = __ldcs(xn + 1 * NC4);
        const float4 xb2 = __ldcs(xn + 2 * NC4);
        const float4 xb3 = __ldcs(xn + 3 * NC4);
        const float4 yb0 = __ldcs(yn + 0 * NC4);
        const float4 yb1 = __ldcs(yn + 1 * NC4);
        const float4 yb2 = __ldcs(yn + 2 * NC4);
        const float4 yb3 = __ldcs(yn + 3 * NC4);

        accum(xa0, ya0, sx2, sy2, sxy, mx);
        accum(xa1, ya1, sx2, sy2, sxy, mx);
        accum(xa2, ya2, sx2, sy2, sxy, mx);
        accum(xa3, ya3, sx2, sy2, sxy, mx);

        xa0 = xb0; xa1 = xb1; xa2 = xb2; xa3 = xb3;
        ya0 = yb0; ya1 = yb1; ya2 = yb2; ya3 = yb3;
    }
    accum(xa0, ya0, sx2, sy2, sxy, mx);
    accum(xa1, ya1, sx2, sy2, sxy, mx);
    accum(xa2, ya2, sx2, sy2, sxy, mx);
    accum(xa3, ya3, sx2, sy2, sxy, mx);

    // ---- Intra-block reduction across the 4 time slices (smem) ----
    __shared__ float4 r_sx2[SLICES - 1][COLS_PER_BLK];
    __shared__ float4 r_sy2[SLICES - 1][COLS_PER_BLK];
    __shared__ float4 r_sxy[SLICES - 1][COLS_PER_BLK];
    __shared__ float4 r_mx [SLICES - 1][COLS_PER_BLK];
    __shared__ bool   s_is_last;

    if (slice > 0) {
        r_sx2[slice - 1][c] = sx2;
        r_sy2[slice - 1][c] = sy2;
        r_sxy[slice - 1][c] = sxy;
        r_mx [slice - 1][c] = mx;
    }
    __syncthreads();

    if (slice == 0) {
#pragma unroll
        for (int s = 0; s < SLICES - 1; s++) {
            const float4 a = r_sx2[s][c];
            const float4 b = r_sy2[s][c];
            const float4 d = r_sxy[s][c];
            const float4 m = r_mx [s][c];
            sx2.x += a.x; sx2.y += a.y; sx2.z += a.z; sx2.w += a.w;
            sy2.x += b.x; sy2.y += b.y; sy2.z += b.z; sy2.w += b.w;
            sxy.x += d.x; sxy.y += d.y; sxy.z += d.z; sxy.w += d.w;
            mx.x = fmaxf(mx.x, m.x); mx.y = fmaxf(mx.y, m.y);
            mx.z = fmaxf(mx.z, m.z); mx.w = fmaxf(mx.w, m.w);
        }
        const int o = blockIdx.y * NC4 + col4;
        g_sx2[o] = sx2;
        g_sy2[o] = sy2;
        g_sxy[o] = sxy;
        g_mx [o] = mx;
        __threadfence();   // release: partials visible before counter bump
    }
    __syncthreads();

    if (threadIdx.x == 0) {
        const unsigned int old = atomicAdd(&g_count[bx], 1u);
        s_is_last = (old == SPLITS - 1);
    }
    __syncthreads();

    if (!s_is_last) return;

    // ---- Finish phase: this is the last y-block for column-block bx ----
    if (threadIdx.x == 0) {
        g_count[bx] = 0;   // reset for next graph replay
        __threadfence();   // acquire side (paired with writers' fences)
    }
    __syncthreads();

    // 512 threads = 4 split-groups x 128 col4. Each thread folds 8 splits.
    const int sg = slice;              // 0..3
    {
        float4 fx2 = make_float4(0.f, 0.f, 0.f, 0.f);
        float4 fy2 = make_float4(0.f, 0.f, 0.f, 0.f);
        float4 fxy = make_float4(0.f, 0.f, 0.f, 0.f);
        float4 fmx = make_float4(0.f, 0.f, 0.f, 0.f);

#pragma unroll
        for (int i = 0; i < SPLITS / SLICES; i++) {
            const int s = sg * (SPLITS / SLICES) + i;
            const int o = s * NC4 + col4;
            const float4 a = ldcg4(&g_sx2[o]);
            const float4 b = ldcg4(&g_sy2[o]);
            const float4 d = ldcg4(&g_sxy[o]);
            const float4 m = ldcg4(&g_mx [o]);
            fx2.x += a.x; fx2.y += a.y; fx2.z += a.z; fx2.w += a.w;
            fy2.x += b.x; fy2.y += b.y; fy2.z += b.z; fy2.w += b.w;
            fxy.x += d.x; fxy.y += d.y; fxy.z += d.z; fxy.w += d.w;
            fmx.x = fmaxf(fmx.x, m.x); fmx.y = fmaxf(fmx.y, m.y);
            fmx.z = fmaxf(fmx.z, m.z); fmx.w = fmaxf(fmx.w, m.w);
        }

        if (sg > 0) {
            r_sx2[sg - 1][c] = fx2;
            r_sy2[sg - 1][c] = fy2;
            r_sxy[sg - 1][c] = fxy;
            r_mx [sg - 1][c] = fmx;
        }
        __syncthreads();

        if (sg == 0) {
#pragma unroll
            for (int s = 0; s < SLICES - 1; s++) {
                const float4 a = r_sx2[s][c];
                const float4 b = r_sy2[s][c];
                const float4 d = r_sxy[s][c];
                const float4 m = r_mx [s][c];
                fx2.x += a.x; fx2.y += a.y; fx2.z += a.z; fx2.w += a.w;
                fy2.x += b.x; fy2.y += b.y; fy2.z += b.z; fy2.w += b.w;
                fxy.x += d.x; fxy.y += d.y; fxy.z += d.z; fxy.w += d.w;
                fmx.x = fmaxf(fmx.x, m.x); fmx.y = fmaxf(fmx.y, m.y);
                fmx.z = fmaxf(fmx.z, m.z); fmx.w = fmaxf(fmx.w, m.w);
            }

            float acc = 0.0f;
            {
                const float ex = DT_CONST * fx2.x + EPS_CONST;
                const float ey = DT_CONST * fy2.x + EPS_CONST;
                if (fmx.x > 0.f) acc += fxy.x / sqrtf(ex * ey);
            }
            {
                const float ex = DT_CONST * fx2.y + EPS_CONST;
                const float ey = DT_CONST * fy2.y + EPS_CONST;
                if (fmx.y > 0.f) acc += fxy.y / sqrtf(ex * ey);
            }
            {
                const float ex = DT_CONST * fx2.z + EPS_CONST;
                const float ey = DT_CONST * fy2.z + EPS_CONST;
                if (fmx.z > 0.f) acc += fxy.z / sqrtf(ex * ey);
            }
            {
                const float ex = DT_CONST * fx2.w + EPS_CONST;
                const float ey = DT_CONST * fy2.w + EPS_CONST;
                if (fmx.w > 0.f) acc += fxy.w / sqrtf(ex * ey);
            }

            // Reduce 128 values (warps 0..3) -> one atomicAdd.
#pragma unroll
            for (int off = 16; off > 0; off >>= 1)
                acc += __shfl_down_sync(0xFFFFFFFFu, acc, off);

            __shared__ float warp_sums[SLICES];
            const int lane = c & 31;
            const int w    = c >> 5;          // 0..3
            if (lane == 0) warp_sums[w] = acc;
            __syncthreads();
            if (c == 0) {
                float v = warp_sums[0] + warp_sums[1] + warp_sums[2] + warp_sums[3];
                atomicAdd(out, v);
            }
        }
    }
}

extern "C" void kernel_launch(void* const* d_in, const int* in_sizes, int n_in,
                              void* d_out, int out_size) {
    const float4* x = (const float4*)d_in[0];
    const float4* y = (const float4*)d_in[1];
    float* out = (float*)d_out;

    ncc_fused<<<dim3(COL_BLOCKS, SPLITS), BLK1>>>(x, y, out);
}

// round 10
// speedup vs baseline: 1.2459x; 1.2459x over previous
#include <cuda_runtime.h>

// NormalizedCrossCorrelation via Parseval identity:
//   sum_k |X_k|^2 = nt * sum_n x_n^2  =>  Ex = DT * sum(x^2) + EPS
//   cc = sum(x*y) / sqrt(Ex*Ey), masked by max|x|>0, summed over all columns.
//
// x,y: [nt=4096, ncol=3072] row-major (columns contiguous).
//
// pass1: grid (12, 16), 512 threads = 8 time-slices x 64 col4 lanes.
//        Each thread streams 32 rows (double-buffered, 8 LDG.128 in flight);
//        slices 1-7 spill to smem, slice 0 folds, writing ONE partial per
//        (split=blockIdx.y, col4): 16 splits, 0.75 MB scratch (L2-resident).
// pass2: 48 blocks x 256 threads; 16 lanes per col4 (2 col4 per warp).
//        lane&15 = split index, shuffle-reduce over 16 lanes, sub-lane 0
//        computes cc for its 4 columns, block reduce, one atomicAdd.

#define NT              4096
#define NCOL            3072
#define NC4             768          // NCOL / 4
#define SPLITS          16           // = pass1 grid.y
#define SLICES          8
#define COLS_PER_BLK    64
#define ROWS_PER_THREAD 32           // NT / SPLITS / SLICES
#define BLK1            (SLICES * COLS_PER_BLK)   // 512
#define COL_BLOCKS      12           // NC4 / COLS_PER_BLK
#define BLK2            256
#define COLS_PER_BLK2   16           // col4 groups per pass2 block (2 per warp)
#define GRID2           (NC4 / COLS_PER_BLK2)     // 48
#define DT_CONST        0.001f
#define EPS_CONST       1e-10f

__device__ float4 g_sx2[SPLITS * NC4];
__device__ float4 g_sy2[SPLITS * NC4];
__device__ float4 g_sxy[SPLITS * NC4];
__device__ float4 g_mx [SPLITS * NC4];

__device__ __forceinline__ void accum(const float4 xv, const float4 yv,
                                      float4& sx2, float4& sy2,
                                      float4& sxy, float4& mx) {
    sx2.x = fmaf(xv.x, xv.x, sx2.x);
    sx2.y = fmaf(xv.y, xv.y, sx2.y);
    sx2.z = fmaf(xv.z, xv.z, sx2.z);
    sx2.w = fmaf(xv.w, xv.w, sx2.w);
    sy2.x = fmaf(yv.x, yv.x, sy2.x);
    sy2.y = fmaf(yv.y, yv.y, sy2.y);
    sy2.z = fmaf(yv.z, yv.z, sy2.z);
    sy2.w = fmaf(yv.w, yv.w, sy2.w);
    sxy.x = fmaf(xv.x, yv.x, sxy.x);
    sxy.y = fmaf(xv.y, yv.y, sxy.y);
    sxy.z = fmaf(xv.z, yv.z, sxy.z);
    sxy.w = fmaf(xv.w, yv.w, sxy.w);
    mx.x = fmaxf(mx.x, fabsf(xv.x));
    mx.y = fmaxf(mx.y, fabsf(xv.y));
    mx.z = fmaxf(mx.z, fabsf(xv.z));
    mx.w = fmaxf(mx.w, fabsf(xv.w));
}

__global__ __launch_bounds__(BLK1, 2) void ncc_pass1(const float4* __restrict__ x,
                                                     const float4* __restrict__ y,
                                                     float* __restrict__ out) {
    if (blockIdx.x == 0 && blockIdx.y == 0 && threadIdx.x == 0)
        out[0] = 0.0f;   // pass2 is stream-ordered after pass1: safe.

    const int c     = threadIdx.x & (COLS_PER_BLK - 1);   // 0..63
    const int slice = threadIdx.x / COLS_PER_BLK;         // 0..7
    const int col4  = blockIdx.x * COLS_PER_BLK + c;      // 0..767
    const int row0  = blockIdx.y * (SLICES * ROWS_PER_THREAD) + slice * ROWS_PER_THREAD;

    float4 sx2 = make_float4(0.f, 0.f, 0.f, 0.f);
    float4 sy2 = make_float4(0.f, 0.f, 0.f, 0.f);
    float4 sxy = make_float4(0.f, 0.f, 0.f, 0.f);
    float4 mx  = make_float4(0.f, 0.f, 0.f, 0.f);

    const float4* xp = x + (size_t)row0 * NC4 + col4;
    const float4* yp = y + (size_t)row0 * NC4 + col4;

    // Double-buffered, 4 rows per stage: 8 LDG.128 always in flight.
    float4 xa0, xa1, xa2, xa3, ya0, ya1, ya2, ya3;
    xa0 = __ldcs(xp + 0 * NC4);
    xa1 = __ldcs(xp + 1 * NC4);
    xa2 = __ldcs(xp + 2 * NC4);
    xa3 = __ldcs(xp + 3 * NC4);
    ya0 = __ldcs(yp + 0 * NC4);
    ya1 = __ldcs(yp + 1 * NC4);
    ya2 = __ldcs(yp + 2 * NC4);
    ya3 = __ldcs(yp + 3 * NC4);

#pragma unroll
    for (int r = 4; r < ROWS_PER_THREAD; r += 4) {
        const float4* xn = xp + (size_t)r * NC4;
        const float4* yn = yp + (size_t)r * NC4;
        const float4 xb0 = __ldcs(xn + 0 * NC4);
        const float4 xb1 = __ldcs(xn + 1 * NC4);
        const float4 xb2 = __ldcs(xn + 2 * NC4);
        const float4 xb3 = __ldcs(xn + 3 * NC4);
        const float4 yb0 = __ldcs(yn + 0 * NC4);
        const float4 yb1 = __ldcs(yn + 1 * NC4);
        const float4 yb2 = __ldcs(yn + 2 * NC4);
        const float4 yb3 = __ldcs(yn + 3 * NC4);

        accum(xa0, ya0, sx2, sy2, sxy, mx);
        accum(xa1, ya1, sx2, sy2, sxy, mx);
        accum(xa2, ya2, sx2, sy2, sxy, mx);
        accum(xa3, ya3, sx2, sy2, sxy, mx);

        xa0 = xb0; xa1 = xb1; xa2 = xb2; xa3 = xb3;
        ya0 = yb0; ya1 = yb1; ya2 = yb2; ya3 = yb3;
    }
    accum(xa0, ya0, sx2, sy2, sxy, mx);
    accum(xa1, ya1, sx2, sy2, sxy, mx);
    accum(xa2, ya2, sx2, sy2, sxy, mx);
    accum(xa3, ya3, sx2, sy2, sxy, mx);

    // Intra-block reduction across the 8 time slices (smem, conflict-free).
    __shared__ float4 r_sx2[SLICES - 1][COLS_PER_BLK];
    __shared__ float4 r_sy2[SLICES - 1][COLS_PER_BLK];
    __shared__ float4 r_sxy[SLICES - 1][COLS_PER_BLK];
    __shared__ float4 r_mx [SLICES - 1][COLS_PER_BLK];

    if (slice > 0) {
        r_sx2[slice - 1][c] = sx2;
        r_sy2[slice - 1][c] = sy2;
        r_sxy[slice - 1][c] = sxy;
        r_mx [slice - 1][c] = mx;
    }
    __syncthreads();

    if (slice == 0) {
#pragma unroll
        for (int s = 0; s < SLICES - 1; s++) {
            const float4 a = r_sx2[s][c];
            const float4 b = r_sy2[s][c];
            const float4 d = r_sxy[s][c];
            const float4 m = r_mx [s][c];
            sx2.x += a.x; sx2.y += a.y; sx2.z += a.z; sx2.w += a.w;
            sy2.x += b.x; sy2.y += b.y; sy2.z += b.z; sy2.w += b.w;
            sxy.x += d.x; sxy.y += d.y; sxy.z += d.z; sxy.w += d.w;
            mx.x = fmaxf(mx.x, m.x); mx.y = fmaxf(mx.y, m.y);
            mx.z = fmaxf(mx.z, m.z); mx.w = fmaxf(mx.w, m.w);
        }
        const int o = blockIdx.y * NC4 + col4;
        g_sx2[o] = sx2;
        g_sy2[o] = sy2;
        g_sxy[o] = sxy;
        g_mx [o] = mx;
    }
}

__device__ __forceinline__ void hsum4(float4& v) {
    // Reduce over 16 lanes (xor offsets stay within the 16-lane half).
#pragma unroll
    for (int off = 8; off > 0; off >>= 1) {
        v.x += __shfl_xor_sync(0xFFFFFFFFu, v.x, off);
        v.y += __shfl_xor_sync(0xFFFFFFFFu, v.y, off);
        v.z += __shfl_xor_sync(0xFFFFFFFFu, v.z, off);
        v.w += __shfl_xor_sync(0xFFFFFFFFu, v.w, off);
    }
}

__device__ __forceinline__ void hmax4(float4& v) {
#pragma unroll
    for (int off = 8; off > 0; off >>= 1) {
        v.x = fmaxf(v.x, __shfl_xor_sync(0xFFFFFFFFu, v.x, off));
        v.y = fmaxf(v.y, __shfl_xor_sync(0xFFFFFFFFu, v.y, off));
        v.z = fmaxf(v.z, __shfl_xor_sync(0xFFFFFFFFu, v.z, off));
        v.w = fmaxf(v.w, __shfl_xor_sync(0xFFFFFFFFu, v.w, off));
    }
}

__global__ __launch_bounds__(BLK2) void ncc_pass2(float* __restrict__ out) {
    const int lane = threadIdx.x & 31;
    const int wid  = threadIdx.x >> 5;            // 0..7
    const int half = lane >> 4;                   // 0..1 (which col4 in warp)
    const int sub  = lane & 15;                   // split index 0..15
    const int col4 = blockIdx.x * COLS_PER_BLK2 + wid * 2 + half;   // 0..767

    const int o = sub * NC4 + col4;
    float4 sx2 = g_sx2[o];
    float4 sy2 = g_sy2[o];
    float4 sxy = g_sxy[o];
    float4 mx  = g_mx [o];

    hsum4(sx2);
    hsum4(sy2);
    hsum4(sxy);
    hmax4(mx);

    __shared__ float part[COLS_PER_BLK2];

    if (sub == 0) {
        float acc = 0.0f;
        {
            const float ex = DT_CONST * sx2.x + EPS_CONST;
            const float ey = DT_CONST * sy2.x + EPS_CONST;
            if (mx.x > 0.f) acc += sxy.x / sqrtf(ex * ey);
        }
        {
            const float ex = DT_CONST * sx2.y + EPS_CONST;
            const float ey = DT_CONST * sy2.y + EPS_CONST;
            if (mx.y > 0.f) acc += sxy.y / sqrtf(ex * ey);
        }
        {
            const float ex = DT_CONST * sx2.z + EPS_CONST;
            const float ey = DT_CONST * sy2.z + EPS_CONST;
            if (mx.z > 0.f) acc += sxy.z / sqrtf(ex * ey);
        }
        {
            const float ex = DT_CONST * sx2.w + EPS_CONST;
            const float ey = DT_CONST * sy2.w + EPS_CONST;
            if (mx.w > 0.f) acc += sxy.w / sqrtf(ex * ey);
        }
        part[wid * 2 + half] = acc;
    }
    __syncthreads();

    if (threadIdx.x == 0) {
        float v = 0.0f;
#pragma unroll
        for (int i = 0; i < COLS_PER_BLK2; i++) v += part[i];
        atomicAdd(out, v);
    }
}

extern "C" void kernel_launch(void* const* d_in, const int* in_sizes, int n_in,
                              void* d_out, int out_size) {
    const float4* x = (const float4*)d_in[0];
    const float4* y = (const float4*)d_in[1];
    float* out = (float*)d_out;

    ncc_pass1<<<dim3(COL_BLOCKS, SPLITS), BLK1>>>(x, y, out);
    ncc_pass2<<<GRID2, BLK2>>>(out);
}

// round 11
// speedup vs baseline: 1.4741x; 1.1832x over previous
#include <cuda_runtime.h>

// NormalizedCrossCorrelation via Parseval identity:
//   sum_k |X_k|^2 = nt * sum_n x_n^2  =>  Ex = DT * sum(x^2) + EPS
//   cc = sum(x*y) / sqrt(Ex*Ey), masked by max|x|>0, summed over all columns.
//
// x,y: [nt=4096, ncol=3072] row-major (columns contiguous).
//
// pass1 (R8 geometry — best measured): grid (6, 32), 512 threads =
//        4 time-slices x 128 col4. Double-buffered streaming (8 LDG.128 in
//        flight), smem slice-fold, one partial per (split, col4): 32 splits,
//        1.5 MB L2 scratch. Triggers programmatic launch completion after
//        its scratch store.
// pass2: 96 blocks x 256 threads, one warp per col4, lane = split. Launched
//        with PDL (programmatic stream serialization): blocks spin up under
//        pass1's tail, cudaGridDependencySynchronize() before reading scratch.

#define NT              4096
#define NCOL            3072
#define NC4             768          // NCOL / 4
#define SPLITS          32           // = pass1 grid.y
#define SLICES          4
#define COLS_PER_BLK    128
#define ROWS_PER_THREAD 32           // NT / SPLITS / SLICES
#define BLK1            (SLICES * COLS_PER_BLK)   // 512
#define COL_BLOCKS      6            // NC4 / COLS_PER_BLK
#define BLK2            256
#define WARPS2          (BLK2 / 32)
#define GRID2           (NC4 / WARPS2)   // 96
#define DT_CONST        0.001f
#define EPS_CONST       1e-10f

__device__ float4 g_sx2[SPLITS * NC4];
__device__ float4 g_sy2[SPLITS * NC4];
__device__ float4 g_sxy[SPLITS * NC4];
__device__ float4 g_mx [SPLITS * NC4];

__device__ __forceinline__ void accum(const float4 xv, const float4 yv,
                                      float4& sx2, float4& sy2,
                                      float4& sxy, float4& mx) {
    sx2.x = fmaf(xv.x, xv.x, sx2.x);
    sx2.y = fmaf(xv.y, xv.y, sx2.y);
    sx2.z = fmaf(xv.z, xv.z, sx2.z);
    sx2.w = fmaf(xv.w, xv.w, sx2.w);
    sy2.x = fmaf(yv.x, yv.x, sy2.x);
    sy2.y = fmaf(yv.y, yv.y, sy2.y);
    sy2.z = fmaf(yv.z, yv.z, sy2.z);
    sy2.w = fmaf(yv.w, yv.w, sy2.w);
    sxy.x = fmaf(xv.x, yv.x, sxy.x);
    sxy.y = fmaf(xv.y, yv.y, sxy.y);
    sxy.z = fmaf(xv.z, yv.z, sxy.z);
    sxy.w = fmaf(xv.w, yv.w, sxy.w);
    mx.x = fmaxf(mx.x, fabsf(xv.x));
    mx.y = fmaxf(mx.y, fabsf(xv.y));
    mx.z = fmaxf(mx.z, fabsf(xv.z));
    mx.w = fmaxf(mx.w, fabsf(xv.w));
}

__global__ __launch_bounds__(BLK1, 2) void ncc_pass1(const float4* __restrict__ x,
                                                     const float4* __restrict__ y,
                                                     float* __restrict__ out) {
    if (blockIdx.x == 0 && blockIdx.y == 0 && threadIdx.x == 0)
        out[0] = 0.0f;   // pass2 gridDependencySynchronizes before touching out

    const int c     = threadIdx.x & (COLS_PER_BLK - 1);   // 0..127
    const int slice = threadIdx.x >> 7;                   // 0..3
    const int col4  = blockIdx.x * COLS_PER_BLK + c;      // 0..767
    const int row0  = blockIdx.y * (SLICES * ROWS_PER_THREAD) + slice * ROWS_PER_THREAD;

    float4 sx2 = make_float4(0.f, 0.f, 0.f, 0.f);
    float4 sy2 = make_float4(0.f, 0.f, 0.f, 0.f);
    float4 sxy = make_float4(0.f, 0.f, 0.f, 0.f);
    float4 mx  = make_float4(0.f, 0.f, 0.f, 0.f);

    const float4* xp = x + (size_t)row0 * NC4 + col4;
    const float4* yp = y + (size_t)row0 * NC4 + col4;

    // Double-buffered, 4 rows per stage: 8 LDG.128 always in flight.
    float4 xa0, xa1, xa2, xa3, ya0, ya1, ya2, ya3;
    xa0 = __ldcs(xp + 0 * NC4);
    xa1 = __ldcs(xp + 1 * NC4);
    xa2 = __ldcs(xp + 2 * NC4);
    xa3 = __ldcs(xp + 3 * NC4);
    ya0 = __ldcs(yp + 0 * NC4);
    ya1 = __ldcs(yp + 1 * NC4);
    ya2 = __ldcs(yp + 2 * NC4);
    ya3 = __ldcs(yp + 3 * NC4);

#pragma unroll
    for (int r = 4; r < ROWS_PER_THREAD; r += 4) {
        const float4* xn = xp + (size_t)r * NC4;
        const float4* yn = yp + (size_t)r * NC4;
        const float4 xb0 = __ldcs(xn + 0 * NC4);
        const float4 xb1 = __ldcs(xn + 1 * NC4);
        const float4 xb2 = __ldcs(xn + 2 * NC4);
        const float4 xb3 = __ldcs(xn + 3 * NC4);
        const float4 yb0 = __ldcs(yn + 0 * NC4);
        const float4 yb1 = __ldcs(yn + 1 * NC4);
        const float4 yb2 = __ldcs(yn + 2 * NC4);
        const float4 yb3 = __ldcs(yn + 3 * NC4);

        accum(xa0, ya0, sx2, sy2, sxy, mx);
        accum(xa1, ya1, sx2, sy2, sxy, mx);
        accum(xa2, ya2, sx2, sy2, sxy, mx);
        accum(xa3, ya3, sx2, sy2, sxy, mx);

        xa0 = xb0; xa1 = xb1; xa2 = xb2; xa3 = xb3;
        ya0 = yb0; ya1 = yb1; ya2 = yb2; ya3 = yb3;
    }
    accum(xa0, ya0, sx2, sy2, sxy, mx);
    accum(xa1, ya1, sx2, sy2, sxy, mx);
    accum(xa2, ya2, sx2, sy2, sxy, mx);
    accum(xa3, ya3, sx2, sy2, sxy, mx);

    // Intra-block reduction across the 4 time slices (smem, conflict-free).
    __shared__ float4 r_sx2[SLICES - 1][COLS_PER_BLK];
    __shared__ float4 r_sy2[SLICES - 1][COLS_PER_BLK];
    __shared__ float4 r_sxy[SLICES - 1][COLS_PER_BLK];
    __shared__ float4 r_mx [SLICES - 1][COLS_PER_BLK];

    if (slice > 0) {
        r_sx2[slice - 1][c] = sx2;
        r_sy2[slice - 1][c] = sy2;
        r_sxy[slice - 1][c] = sxy;
        r_mx [slice - 1][c] = mx;
    }
    __syncthreads();

    if (slice == 0) {
#pragma unroll
        for (int s = 0; s < SLICES - 1; s++) {
            const float4 a = r_sx2[s][c];
            const float4 b = r_sy2[s][c];
            const float4 d = r_sxy[s][c];
            const float4 m = r_mx [s][c];
            sx2.x += a.x; sx2.y += a.y; sx2.z += a.z; sx2.w += a.w;
            sy2.x += b.x; sy2.y += b.y; sy2.z += b.z; sy2.w += b.w;
            sxy.x += d.x; sxy.y += d.y; sxy.z += d.z; sxy.w += d.w;
            mx.x = fmaxf(mx.x, m.x); mx.y = fmaxf(mx.y, m.y);
            mx.z = fmaxf(mx.z, m.z); mx.w = fmaxf(mx.w, m.w);
        }
        const int o = blockIdx.y * NC4 + col4;
        g_sx2[o] = sx2;
        g_sy2[o] = sy2;
        g_sxy[o] = sxy;
        g_mx [o] = mx;
    }

    // All scratch writes done: allow the PDL-dependent pass2 to proceed.
    cudaTriggerProgrammaticLaunchCompletion();
}

__device__ __forceinline__ void wsum4(float4& v) {
#pragma unroll
    for (int off = 16; off > 0; off >>= 1) {
        v.x += __shfl_xor_sync(0xFFFFFFFFu, v.x, off);
        v.y += __shfl_xor_sync(0xFFFFFFFFu, v.y, off);
        v.z += __shfl_xor_sync(0xFFFFFFFFu, v.z, off);
        v.w += __shfl_xor_sync(0xFFFFFFFFu, v.w, off);
    }
}

__device__ __forceinline__ void wmax4(float4& v) {
#pragma unroll
    for (int off = 16; off > 0; off >>= 1) {
        v.x = fmaxf(v.x, __shfl_xor_sync(0xFFFFFFFFu, v.x, off));
        v.y = fmaxf(v.y, __shfl_xor_sync(0xFFFFFFFFu, v.y, off));
        v.z = fmaxf(v.z, __shfl_xor_sync(0xFFFFFFFFu, v.z, off));
        v.w = fmaxf(v.w, __shfl_xor_sync(0xFFFFFFFFu, v.w, off));
    }
}

__global__ __launch_bounds__(BLK2) void ncc_pass2(float* __restrict__ out) {
    const int lane = threadIdx.x & 31;
    const int wid  = threadIdx.x >> 5;
    const int col4 = blockIdx.x * WARPS2 + wid;   // 0..767, one warp per col4
    const int o    = lane * NC4 + col4;           // lane = split index

    // Wait for pass1's grid (PDL edge) before reading scratch / out.
    cudaGridDependencySynchronize();

    float4 sx2 = g_sx2[o];
    float4 sy2 = g_sy2[o];
    float4 sxy = g_sxy[o];
    float4 mx  = g_mx [o];

    wsum4(sx2);
    wsum4(sy2);
    wsum4(sxy);
    wmax4(mx);

    __shared__ float warp_sums[WARPS2];

    if (lane == 0) {
        float acc = 0.0f;
        {
            const float ex = DT_CONST * sx2.x + EPS_CONST;
            const float ey = DT_CONST * sy2.x + EPS_CONST;
            if (mx.x > 0.f) acc += sxy.x / sqrtf(ex * ey);
        }
        {
            const float ex = DT_CONST * sx2.y + EPS_CONST;
            const float ey = DT_CONST * sy2.y + EPS_CONST;
            if (mx.y > 0.f) acc += sxy.y / sqrtf(ex * ey);
        }
        {
            const float ex = DT_CONST * sx2.z + EPS_CONST;
            const float ey = DT_CONST * sy2.z + EPS_CONST;
            if (mx.z > 0.f) acc += sxy.z / sqrtf(ex * ey);
        }
        {
            const float ex = DT_CONST * sx2.w + EPS_CONST;
            const float ey = DT_CONST * sy2.w + EPS_CONST;
            if (mx.w > 0.f) acc += sxy.w / sqrtf(ex * ey);
        }
        warp_sums[wid] = acc;
    }
    __syncthreads();

    if (threadIdx.x == 0) {
        float v = 0.0f;
#pragma unroll
        for (int w = 0; w < WARPS2; w++) v += warp_sums[w];
        atomicAdd(out, v);
    }
}

extern "C" void kernel_launch(void* const* d_in, const int* in_sizes, int n_in,
                              void* d_out, int out_size) {
    const float4* x = (const float4*)d_in[0];
    const float4* y = (const float4*)d_in[1];
    float* out = (float*)d_out;

    ncc_pass1<<<dim3(COL_BLOCKS, SPLITS), BLK1>>>(x, y, out);

    // pass2 with Programmatic Dependent Launch: overlap its launch/ramp with
    // pass1's tail; correctness guarded by cudaGridDependencySynchronize().
    cudaLaunchAttribute attrs[1];
    attrs[0].id = cudaLaunchAttributeProgrammaticStreamSerialization;
    attrs[0].val.programmaticStreamSerializationAllowed = 1;

    cudaLaunchConfig_t cfg = {};
    cfg.gridDim  = dim3(GRID2, 1, 1);
    cfg.blockDim = dim3(BLK2, 1, 1);
    cfg.dynamicSmemBytes = 0;
    cfg.stream = 0;
    cfg.attrs = attrs;
    cfg.numAttrs = 1;

    cudaLaunchKernelEx(&cfg, ncc_pass2, out);
}

// round 13
// speedup vs baseline: 1.4773x; 1.0022x over previous
#include <cuda_runtime.h>

// NormalizedCrossCorrelation via Parseval identity:
//   sum_k |X_k|^2 = nt * sum_n x_n^2  =>  Ex = DT * sum(x^2) + EPS
//   cc = sum(x*y) / sqrt(Ex*Ey), masked by max|x|>0, summed over all columns.
//
// x,y: [nt=4096, ncol=3072] row-major (columns contiguous).
//
// pass1: grid (6, 32), 512 threads = 4 time-slices x 128 col4 lanes.
//        Double-buffered streaming (8 LDG.128 in flight), smem slice-fold,
//        one 64B stat record per (col4, split) into interleaved scratch
//        g_stats[col4][split] = {sx2, sy2, sxy, mx}  (1.5 MB, L2-resident).
//        Triggers programmatic launch completion after the scratch store.
// pass2: 96 blocks x 256 threads, one warp per col4, lane = split. PDL launch:
//        blocks ramp up under pass1's tail, cudaGridDependencySynchronize()
//        before reading scratch. Each warp reads ONE contiguous 2KB span
//        (perfectly coalesced), shuffle-reduces, one atomicAdd per block.

#define NT              4096
#define NCOL            3072
#define NC4             768          // NCOL / 4
#define SPLITS          32           // = pass1 grid.y = warp lanes in pass2
#define SLICES          4
#define COLS_PER_BLK    128
#define ROWS_PER_THREAD 32           // NT / SPLITS / SLICES
#define BLK1            (SLICES * COLS_PER_BLK)   // 512
#define COL_BLOCKS      6            // NC4 / COLS_PER_BLK
#define BLK2            256
#define WARPS2          (BLK2 / 32)
#define GRID2           (NC4 / WARPS2)   // 96
#define DT_CONST        0.001f
#define EPS_CONST       1e-10f

// Interleaved scratch: record (col4, split) = 4 float4s {sx2, sy2, sxy, mx}.
// Index of record = col4 * SPLITS + split; float4 index = record * 4 + k.
__device__ float4 g_stats[NC4 * SPLITS * 4];

__device__ __forceinline__ void accum(const float4 xv, const float4 yv,
                                      float4& sx2, float4& sy2,
                                      float4& sxy, float4& mx) {
    sx2.x = fmaf(xv.x, xv.x, sx2.x);
    sx2.y = fmaf(xv.y, xv.y, sx2.y);
    sx2.z = fmaf(xv.z, xv.z, sx2.z);
    sx2.w = fmaf(xv.w, xv.w, sx2.w);
    sy2.x = fmaf(yv.x, yv.x, sy2.x);
    sy2.y = fmaf(yv.y, yv.y, sy2.y);
    sy2.z = fmaf(yv.z, yv.z, sy2.z);
    sy2.w = fmaf(yv.w, yv.w, sy2.w);
    sxy.x = fmaf(xv.x, yv.x, sxy.x);
    sxy.y = fmaf(xv.y, yv.y, sxy.y);
    sxy.z = fmaf(xv.z, yv.z, sxy.z);
    sxy.w = fmaf(xv.w, yv.w, sxy.w);
    mx.x = fmaxf(mx.x, fabsf(xv.x));
    mx.y = fmaxf(mx.y, fabsf(xv.y));
    mx.z = fmaxf(mx.z, fabsf(xv.z));
    mx.w = fmaxf(mx.w, fabsf(xv.w));
}

__global__ __launch_bounds__(BLK1, 2) void ncc_pass1(const float4* __restrict__ x,
                                                     const float4* __restrict__ y,
                                                     float* __restrict__ out) {
    if (blockIdx.x == 0 && blockIdx.y == 0 && threadIdx.x == 0)
        out[0] = 0.0f;   // pass2 gridDependencySynchronizes before touching out

    const int c     = threadIdx.x & (COLS_PER_BLK - 1);   // 0..127
    const int slice = threadIdx.x >> 7;                   // 0..3
    const int col4  = blockIdx.x * COLS_PER_BLK + c;      // 0..767
    const int row0  = blockIdx.y * (SLICES * ROWS_PER_THREAD) + slice * ROWS_PER_THREAD;

    float4 sx2 = make_float4(0.f, 0.f, 0.f, 0.f);
    float4 sy2 = make_float4(0.f, 0.f, 0.f, 0.f);
    float4 sxy = make_float4(0.f, 0.f, 0.f, 0.f);
    float4 mx  = make_float4(0.f, 0.f, 0.f, 0.f);

    const float4* xp = x + (size_t)row0 * NC4 + col4;
    const float4* yp = y + (size_t)row0 * NC4 + col4;

    // Double-buffered, 4 rows per stage: 8 LDG.128 always in flight.
    float4 xa0, xa1, xa2, xa3, ya0, ya1, ya2, ya3;
    xa0 = __ldcs(xp + 0 * NC4);
    xa1 = __ldcs(xp + 1 * NC4);
    xa2 = __ldcs(xp + 2 * NC4);
    xa3 = __ldcs(xp + 3 * NC4);
    ya0 = __ldcs(yp + 0 * NC4);
    ya1 = __ldcs(yp + 1 * NC4);
    ya2 = __ldcs(yp + 2 * NC4);
    ya3 = __ldcs(yp + 3 * NC4);

#pragma unroll
    for (int r = 4; r < ROWS_PER_THREAD; r += 4) {
        const float4* xn = xp + (size_t)r * NC4;
        const float4* yn = yp + (size_t)r * NC4;
        const float4 xb0 = __ldcs(xn + 0 * NC4);
        const float4 xb1 = __ldcs(xn + 1 * NC4);
        const float4 xb2 = __ldcs(xn + 2 * NC4);
        const float4 xb3 = __ldcs(xn + 3 * NC4);
        const float4 yb0 = __ldcs(yn + 0 * NC4);
        const float4 yb1 = __ldcs(yn + 1 * NC4);
        const float4 yb2 = __ldcs(yn + 2 * NC4);
        const float4 yb3 = __ldcs(yn + 3 * NC4);

        accum(xa0, ya0, sx2, sy2, sxy, mx);
        accum(xa1, ya1, sx2, sy2, sxy, mx);
        accum(xa2, ya2, sx2, sy2, sxy, mx);
        accum(xa3, ya3, sx2, sy2, sxy, mx);

        xa0 = xb0; xa1 = xb1; xa2 = xb2; xa3 = xb3;
        ya0 = yb0; ya1 = yb1; ya2 = yb2; ya3 = yb3;
    }
    accum(xa0, ya0, sx2, sy2, sxy, mx);
    accum(xa1, ya1, sx2, sy2, sxy, mx);
    accum(xa2, ya2, sx2, sy2, sxy, mx);
    accum(xa3, ya3, sx2, sy2, sxy, mx);

    // Intra-block reduction across the 4 time slices (smem, conflict-free).
    __shared__ float4 r_sx2[SLICES - 1][COLS_PER_BLK];
    __shared__ float4 r_sy2[SLICES - 1][COLS_PER_BLK];
    __shared__ float4 r_sxy[SLICES - 1][COLS_PER_BLK];
    __shared__ float4 r_mx [SLICES - 1][COLS_PER_BLK];

    if (slice > 0) {
        r_sx2[slice - 1][c] = sx2;
        r_sy2[slice - 1][c] = sy2;
        r_sxy[slice - 1][c] = sxy;
        r_mx [slice - 1][c] = mx;
    }
    __syncthreads();

    if (slice == 0) {
#pragma unroll
        for (int s = 0; s < SLICES - 1; s++) {
            const float4 a = r_sx2[s][c];
            const float4 b = r_sy2[s][c];
            const float4 d = r_sxy[s][c];
            const float4 m = r_mx [s][c];
            sx2.x += a.x; sx2.y += a.y; sx2.z += a.z; sx2.w += a.w;
            sy2.x += b.x; sy2.y += b.y; sy2.z += b.z; sy2.w += b.w;
            sxy.x += d.x; sxy.y += d.y; sxy.z += d.z; sxy.w += d.w;
            mx.x = fmaxf(mx.x, m.x); mx.y = fmaxf(mx.y, m.y);
            mx.z = fmaxf(mx.z, m.z); mx.w = fmaxf(mx.w, m.w);
        }
        // Interleaved record: 64B contiguous per (col4, split).
        const int rec = (col4 * SPLITS + blockIdx.y) * 4;
        g_stats[rec + 0] = sx2;
        g_stats[rec + 1] = sy2;
        g_stats[rec + 2] = sxy;
        g_stats[rec + 3] = mx;
    }

    // All scratch writes done: allow the PDL-dependent pass2 to proceed.
    cudaTriggerProgrammaticLaunchCompletion();
}

__device__ __forceinline__ void wsum4(float4& v) {
#pragma unroll
    for (int off = 16; off > 0; off >>= 1) {
        v.x += __shfl_xor_sync(0xFFFFFFFFu, v.x, off);
        v.y += __shfl_xor_sync(0xFFFFFFFFu, v.y, off);
        v.z += __shfl_xor_sync(0xFFFFFFFFu, v.z, off);
        v.w += __shfl_xor_sync(0xFFFFFFFFu, v.w, off);
    }
}

__device__ __forceinline__ void wmax4(float4& v) {
#pragma unroll
    for (int off = 16; off > 0; off >>= 1) {
        v.x = fmaxf(v.x, __shfl_xor_sync(0xFFFFFFFFu, v.x, off));
        v.y = fmaxf(v.y, __shfl_xor_sync(0xFFFFFFFFu, v.y, off));
        v.z = fmaxf(v.z, __shfl_xor_sync(0xFFFFFFFFu, v.z, off));
        v.w = fmaxf(v.w, __shfl_xor_sync(0xFFFFFFFFu, v.w, off));
    }
}

__global__ __launch_bounds__(BLK2) void ncc_pass2(float* __restrict__ out) {
    const int lane = threadIdx.x & 31;
    const int wid  = threadIdx.x >> 5;
    const int col4 = blockIdx.x * WARPS2 + wid;   // 0..767, one warp per col4
    const int rec  = (col4 * SPLITS + lane) * 4;  // lane = split; 64B record

    // Wait for pass1's grid (PDL edge) before reading scratch / out.
    cudaGridDependencySynchronize();

    // Warp reads one contiguous 2KB span: fully coalesced L2 traffic.
    float4 sx2 = g_stats[rec + 0];
    float4 sy2 = g_stats[rec + 1];
    float4 sxy = g_stats[rec + 2];
    float4 mx  = g_stats[rec + 3];

    wsum4(sx2);
    wsum4(sy2);
    wsum4(sxy);
    wmax4(mx);

    __shared__ float warp_sums[WARPS2];

    if (lane == 0) {
        float acc = 0.0f;
        {
            const float ex = DT_CONST * sx2.x + EPS_CONST;
            const float ey = DT_CONST * sy2.x + EPS_CONST;
            if (mx.x > 0.f) acc += sxy.x / sqrtf(ex * ey);
        }
        {
            const float ex = DT_CONST * sx2.y + EPS_CONST;
            const float ey = DT_CONST * sy2.y + EPS_CONST;
            if (mx.y > 0.f) acc += sxy.y / sqrtf(ex * ey);
        }
        {
            const float ex = DT_CONST * sx2.z + EPS_CONST;
            const float ey = DT_CONST * sy2.z + EPS_CONST;
            if (mx.z > 0.f) acc += sxy.z / sqrtf(ex * ey);
        }
        {
            const float ex = DT_CONST * sx2.w + EPS_CONST;
            const float ey = DT_CONST * sy2.w + EPS_CONST;
            if (mx.w > 0.f) acc += sxy.w / sqrtf(ex * ey);
        }
        warp_sums[wid] = acc;
    }
    __syncthreads();

    if (threadIdx.x == 0) {
        float v = 0.0f;
#pragma unroll
        for (int w = 0; w < WARPS2; w++) v += warp_sums[w];
        atomicAdd(out, v);
    }
}

extern "C" void kernel_launch(void* const* d_in, const int* in_sizes, int n_in,
                              void* d_out, int out_size) {
    const float4* x = (const float4*)d_in[0];
    const float4* y = (const float4*)d_in[1];
    float* out = (float*)d_out;

    ncc_pass1<<<dim3(COL_BLOCKS, SPLITS), BLK1>>>(x, y, out);

    // pass2 with Programmatic Dependent Launch: overlap its launch/ramp with
    // pass1's tail; correctness guarded by cudaGridDependencySynchronize().
    cudaLaunchAttribute attrs[1];
    attrs[0].id = cudaLaunchAttributeProgrammaticStreamSerialization;
    attrs[0].val.programmaticStreamSerializationAllowed = 1;

    cudaLaunchConfig_t cfg = {};
    cfg.gridDim  = dim3(GRID2, 1, 1);
    cfg.blockDim = dim3(BLK2, 1, 1);
    cfg.dynamicSmemBytes = 0;
    cfg.stream = 0;
    cfg.attrs = attrs;
    cfg.numAttrs = 1;

    cudaLaunchKernelEx(&cfg, ncc_pass2, out);
}